// round 11
// baseline (speedup 1.0000x reference)
#include <cuda_runtime.h>
#include <cuda_fp16.h>
#include <cstdint>

// out[m,n] = f32( f16( f32x[m,:] . (W[n,:]*scale) ) + f16(bias[n]) )
// Harness dtypes: x f32 [M,K], weight i32-or-i8 (probed) [N,K],
// scale f32 [N,K/128], bias f32 [N], out f32 [M,N]
// compute_103 virtual arch: NO tcgen05. Ceiling = legacy HMMA (~610 TF/s).
// R6: R4 tile config (occ=2 is load-bearing) + single-sync pipelined mainloop.

#define M_TOTAL 8192
#define N_TOTAL 11008
#define K_TOTAL 4096
#define GROUPSZ 128

#define BM 128
#define BN 128
#define BK 64
#define NSTAGE 3
#define NT (K_TOTAL / BK)   // 64
#define LDS_A 72            // 64 + 8 pad halves; 144B stride -> conflict-free ldmatrix
#define LDS_B 72

#define SMEM_BYTES (NSTAGE * (BM * LDS_A + BN * LDS_B) * 2)  // 110592 -> 2 CTAs/SM

// ---------------- scratch (f16 prepass outputs) ----------------
__device__ __half g_Ah[(size_t)M_TOTAL * K_TOTAL];   // 64 MB
__device__ __half g_Bh[(size_t)N_TOTAL * K_TOTAL];   // 88 MB
__device__ int    g_w_is_i32;

__device__ __forceinline__ uint32_t smem_u32(const void* p) {
    uint32_t a;
    asm("{ .reg .u64 t; cvta.to.shared.u64 t, %1; cvt.u32.u64 %0, t; }"
        : "=r"(a) : "l"(p));
    return a;
}

#define CP_ASYNC_16(dst_u32, src_ptr) \
    asm volatile("cp.async.cg.shared.global [%0], [%1], 16;" \
                 :: "r"(dst_u32), "l"(src_ptr) : "memory")
#define CP_COMMIT() asm volatile("cp.async.commit_group;" ::: "memory")
#define CP_WAIT(n)  asm volatile("cp.async.wait_group %0;" :: "n"(n) : "memory")

// ---------------- dtype probe ----------------
__global__ void probe_weight_kernel(const int8_t* __restrict__ w)
{
    if (threadIdx.x != 0 || blockIdx.x != 0) return;
    int votes = 0;
#pragma unroll
    for (int i = 0; i < 16; i++) {
        int8_t b0 = w[i * 4 + 0], b1 = w[i * 4 + 1], b2 = w[i * 4 + 2], b3 = w[i * 4 + 3];
        int8_t ext = (b0 < 0) ? (int8_t)-1 : (int8_t)0;
        if (b1 == ext && b2 == ext && b3 == ext) votes++;
    }
    g_w_is_i32 = (votes >= 14) ? 1 : 0;
}

// ---------------- prepass: x f32 -> f16 ----------------
__global__ __launch_bounds__(256) void convert_x_kernel(const float4* __restrict__ X)
{
    size_t i = (size_t)blockIdx.x * 256 + threadIdx.x;  // 8 floats / thread
    float4 a = X[2 * i], b = X[2 * i + 1];
    __half2 h0 = __floats2half2_rn(a.x, a.y);
    __half2 h1 = __floats2half2_rn(a.z, a.w);
    __half2 h2 = __floats2half2_rn(b.x, b.y);
    __half2 h3 = __floats2half2_rn(b.z, b.w);
    uint4 pk;
    pk.x = *(const uint32_t*)&h0; pk.y = *(const uint32_t*)&h1;
    pk.z = *(const uint32_t*)&h2; pk.w = *(const uint32_t*)&h3;
    reinterpret_cast<uint4*>(g_Ah)[i] = pk;
}

// ---------------- prepass: W dequant -> f16 ----------------
__global__ __launch_bounds__(256) void dequant_w_kernel(const void* __restrict__ Wv,
                                                        const float* __restrict__ S)
{
    size_t i = (size_t)blockIdx.x * 256 + threadIdx.x;  // 8 weights / thread
    size_t base = i * 8;
    int n = (int)(base / K_TOTAL);
    int k = (int)(base % K_TOTAL);
    float sc = S[(size_t)n * (K_TOTAL / GROUPSZ) + (k >> 7)];

    float f[8];
    if (g_w_is_i32) {
        const int4* W = reinterpret_cast<const int4*>(Wv);
        int4 v0 = W[i * 2], v1 = W[i * 2 + 1];
        f[0] = (float)v0.x; f[1] = (float)v0.y; f[2] = (float)v0.z; f[3] = (float)v0.w;
        f[4] = (float)v1.x; f[5] = (float)v1.y; f[6] = (float)v1.z; f[7] = (float)v1.w;
    } else {
        uint2 raw = reinterpret_cast<const uint2*>(Wv)[i];
        const int8_t* b = reinterpret_cast<const int8_t*>(&raw);
#pragma unroll
        for (int j = 0; j < 8; j++) f[j] = (float)b[j];
    }
    __half2 h0 = __floats2half2_rn(f[0] * sc, f[1] * sc);
    __half2 h1 = __floats2half2_rn(f[2] * sc, f[3] * sc);
    __half2 h2 = __floats2half2_rn(f[4] * sc, f[5] * sc);
    __half2 h3 = __floats2half2_rn(f[6] * sc, f[7] * sc);
    uint4 pk;
    pk.x = *(const uint32_t*)&h0; pk.y = *(const uint32_t*)&h1;
    pk.z = *(const uint32_t*)&h2; pk.w = *(const uint32_t*)&h3;
    reinterpret_cast<uint4*>(g_Bh)[i] = pk;
}

// ---------------- HMMA GEMM: 128x128 tile, single-sync 3-stage pipeline --------
__global__ __launch_bounds__(256, 2) void wq8_gemm_kernel(
    const float* __restrict__ BIAS,
    float* __restrict__ O)
{
    extern __shared__ __align__(16) __half smem[];
    __half (*As)[BM][LDS_A] = reinterpret_cast<__half (*)[BM][LDS_A]>(smem);
    __half (*Bs)[BN][LDS_B] =
        reinterpret_cast<__half (*)[BN][LDS_B]>(smem + NSTAGE * BM * LDS_A);

    const int tid  = threadIdx.x;
    const int lane = tid & 31;
    const int warp = tid >> 5;
    const int wm   = warp >> 2;   // 0..1 : 64-row slab
    const int wn   = warp & 3;    // 0..3 : 32-col slab

    const int m0 = blockIdx.y * BM;
    const int n0 = blockIdx.x * BN;

    float acc[4][4][4];
#pragma unroll
    for (int i = 0; i < 4; i++)
#pragma unroll
        for (int j = 0; j < 4; j++)
#pragma unroll
            for (int k = 0; k < 4; k++) acc[i][j][k] = 0.f;

    // per-thread load plan: tile 128 rows x 64 halves = 1024 x 16B chunks
    // = 4 chunks/thread (A and B alike)
    const int l_row = tid >> 3;          // base row 0..31 (+32*i)
    const int l_col = (tid & 7) * 8;     // half offset

    auto issue_stage = [&](int s, int kb) {
#pragma unroll
        for (int i = 0; i < 4; i++) {
            int row = l_row + i * 32;
            uint32_t d = smem_u32(&As[s][row][l_col]);
            CP_ASYNC_16(d, g_Ah + (size_t)(m0 + row) * K_TOTAL + kb + l_col);
        }
#pragma unroll
        for (int i = 0; i < 4; i++) {
            int row = l_row + i * 32;
            uint32_t d = smem_u32(&Bs[s][row][l_col]);
            CP_ASYNC_16(d, g_Bh + (size_t)(n0 + row) * K_TOTAL + kb + l_col);
        }
    };

    auto compute = [&](int s) {
#pragma unroll
        for (int ks = 0; ks < 4; ks++) {
            uint32_t af[4][4];
#pragma unroll
            for (int mi = 0; mi < 4; mi++) {
                const __half* p =
                    &As[s][wm * 64 + mi * 16 + (lane & 15)][ks * 16 + (lane >> 4) * 8];
                uint32_t addr = smem_u32(p);
                asm volatile(
                    "ldmatrix.sync.aligned.m8n8.x4.shared.b16 {%0,%1,%2,%3}, [%4];"
                    : "=r"(af[mi][0]), "=r"(af[mi][1]), "=r"(af[mi][2]), "=r"(af[mi][3])
                    : "r"(addr));
            }
            uint32_t bf[8];
#pragma unroll
            for (int bi = 0; bi < 2; bi++) {
                int mm = lane >> 3;
                int nr = wn * 32 + bi * 16 + ((mm >> 1) << 3) + (lane & 7);
                int kk = ks * 16 + ((mm & 1) << 3);
                uint32_t addr = smem_u32(&Bs[s][nr][kk]);
                asm volatile(
                    "ldmatrix.sync.aligned.m8n8.x4.shared.b16 {%0,%1,%2,%3}, [%4];"
                    : "=r"(bf[bi * 4]), "=r"(bf[bi * 4 + 1]),
                      "=r"(bf[bi * 4 + 2]), "=r"(bf[bi * 4 + 3])
                    : "r"(addr));
            }
#pragma unroll
            for (int mi = 0; mi < 4; mi++)
#pragma unroll
                for (int ni = 0; ni < 4; ni++) {
                    asm volatile(
                        "mma.sync.aligned.m16n8k16.row.col.f32.f16.f16.f32 "
                        "{%0,%1,%2,%3}, {%4,%5,%6,%7}, {%8,%9}, {%0,%1,%2,%3};"
                        : "+f"(acc[mi][ni][0]), "+f"(acc[mi][ni][1]),
                          "+f"(acc[mi][ni][2]), "+f"(acc[mi][ni][3])
                        : "r"(af[mi][0]), "r"(af[mi][1]), "r"(af[mi][2]), "r"(af[mi][3]),
                          "r"(bf[ni * 2]), "r"(bf[ni * 2 + 1]));
                }
        }
    };

    // prologue: fill 2 of 3 stages
#pragma unroll
    for (int s = 0; s < NSTAGE - 1; s++) {
        issue_stage(s, s * BK);
        CP_COMMIT();
    }

    // mainloop: ONE sync per iteration; loads for stage t+2 issued before compute(t).
    // Safe: stage (t+2)%3 == (t-1)%3 was consumed at iter t-1, and every thread
    // passed this iteration's sync after its own compute(t-1).
    for (int t = 0; t < NT; t++) {
        CP_WAIT(NSTAGE - 2);     // stage t resident (at most 1 group still pending)
        __syncthreads();
        if (t + NSTAGE - 1 < NT)
            issue_stage((t + NSTAGE - 1) % NSTAGE, (t + NSTAGE - 1) * BK);
        CP_COMMIT();             // empty group in tail keeps wait-count invariant
        compute(t % NSTAGE);
    }

    // ---- epilogue: f16(acc) + f16(bias), store f32 (matches reference rounding) ----
#pragma unroll
    for (int mi = 0; mi < 4; mi++) {
#pragma unroll
        for (int ni = 0; ni < 4; ni++) {
            int col = n0 + wn * 32 + ni * 8 + (lane & 3) * 2;
            float2 bf2 = *reinterpret_cast<const float2*>(BIAS + col);
            __half2 b2 = __floats2half2_rn(bf2.x, bf2.y);
            int r0 = m0 + wm * 64 + mi * 16 + (lane >> 2);

            __half2 v0 = __floats2half2_rn(acc[mi][ni][0], acc[mi][ni][1]);
            __half2 v1 = __floats2half2_rn(acc[mi][ni][2], acc[mi][ni][3]);
            float2 o0 = __half22float2(__hadd2(v0, b2));
            float2 o1 = __half22float2(__hadd2(v1, b2));
            *reinterpret_cast<float2*>(O + (size_t)r0 * N_TOTAL + col) = o0;
            *reinterpret_cast<float2*>(O + (size_t)(r0 + 8) * N_TOTAL + col) = o1;
        }
    }
}

extern "C" void kernel_launch(void* const* d_in, const int* in_sizes, int n_in,
                              void* d_out, int out_size)
{
    const float* x    = (const float*)d_in[0];
    const void*  w    = (const void*)d_in[1];
    const float* s    = (const float*)d_in[2];
    const float* bias = (const float*)d_in[3];
    float*       out  = (float*)d_out;

    cudaFuncSetAttribute(wq8_gemm_kernel,
                         cudaFuncAttributeMaxDynamicSharedMemorySize, SMEM_BYTES);

    probe_weight_kernel<<<1, 32>>>((const int8_t*)w);
    convert_x_kernel<<<(int)((size_t)M_TOTAL * K_TOTAL / 8 / 256), 256>>>(
        (const float4*)x);
    dequant_w_kernel<<<(int)((size_t)N_TOTAL * K_TOTAL / 8 / 256), 256>>>(w, s);

    dim3 grid(N_TOTAL / BN, M_TOTAL / BM);  // 86 x 64
    wq8_gemm_kernel<<<grid, 256, SMEM_BYTES>>>(bias, out);
}

// round 12
// speedup vs baseline: 1.0680x; 1.0680x over previous
#include <cuda_runtime.h>
#include <cuda_fp16.h>
#include <cstdint>

// out[m,n] = f32( f16( f32x[m,:] . (W[n,:]*scale) ) + f16(bias[n]) )
// Harness dtypes: x f32 [M,K], weight i32-or-i8 (probed) [N,K],
// scale f32 [N,K/128], bias f32 [N], out f32 [M,N]
// compute_103 virtual arch: NO tcgen05. Ceiling = legacy HMMA (~610 TF/s).
// R7: 128x256 tile with 512 threads -> 16 warps/SM (R4's warp profile) +
//     R5's L2 reuse. Single sync, cp.async issued after compute.

#define M_TOTAL 8192
#define N_TOTAL 11008
#define K_TOTAL 4096
#define GROUPSZ 128

#define BM 128
#define BN 256
#define BK 64
#define NSTAGE 3
#define NT (K_TOTAL / BK)   // 64
#define LDS_A 72            // 64 + 8 pad halves; conflict-free ldmatrix
#define LDS_B 72
#define THREADS 512

#define SMEM_BYTES (NSTAGE * (BM * LDS_A + BN * LDS_B) * 2)  // 165888

// ---------------- scratch (f16 prepass outputs) ----------------
__device__ __half g_Ah[(size_t)M_TOTAL * K_TOTAL];   // 64 MB
__device__ __half g_Bh[(size_t)N_TOTAL * K_TOTAL];   // 88 MB
__device__ int    g_w_is_i32;

__device__ __forceinline__ uint32_t smem_u32(const void* p) {
    uint32_t a;
    asm("{ .reg .u64 t; cvta.to.shared.u64 t, %1; cvt.u32.u64 %0, t; }"
        : "=r"(a) : "l"(p));
    return a;
}

#define CP_ASYNC_16(dst_u32, src_ptr) \
    asm volatile("cp.async.cg.shared.global [%0], [%1], 16;" \
                 :: "r"(dst_u32), "l"(src_ptr) : "memory")
#define CP_COMMIT() asm volatile("cp.async.commit_group;" ::: "memory")
#define CP_WAIT(n)  asm volatile("cp.async.wait_group %0;" :: "n"(n) : "memory")

// ---------------- dtype probe ----------------
__global__ void probe_weight_kernel(const int8_t* __restrict__ w)
{
    if (threadIdx.x != 0 || blockIdx.x != 0) return;
    int votes = 0;
#pragma unroll
    for (int i = 0; i < 16; i++) {
        int8_t b0 = w[i * 4 + 0], b1 = w[i * 4 + 1], b2 = w[i * 4 + 2], b3 = w[i * 4 + 3];
        int8_t ext = (b0 < 0) ? (int8_t)-1 : (int8_t)0;
        if (b1 == ext && b2 == ext && b3 == ext) votes++;
    }
    g_w_is_i32 = (votes >= 14) ? 1 : 0;
}

// ---------------- prepass: x f32 -> f16 ----------------
__global__ __launch_bounds__(256) void convert_x_kernel(const float4* __restrict__ X)
{
    size_t i = (size_t)blockIdx.x * 256 + threadIdx.x;  // 8 floats / thread
    float4 a = X[2 * i], b = X[2 * i + 1];
    __half2 h0 = __floats2half2_rn(a.x, a.y);
    __half2 h1 = __floats2half2_rn(a.z, a.w);
    __half2 h2 = __floats2half2_rn(b.x, b.y);
    __half2 h3 = __floats2half2_rn(b.z, b.w);
    uint4 pk;
    pk.x = *(const uint32_t*)&h0; pk.y = *(const uint32_t*)&h1;
    pk.z = *(const uint32_t*)&h2; pk.w = *(const uint32_t*)&h3;
    reinterpret_cast<uint4*>(g_Ah)[i] = pk;
}

// ---------------- prepass: W dequant -> f16 ----------------
__global__ __launch_bounds__(256) void dequant_w_kernel(const void* __restrict__ Wv,
                                                        const float* __restrict__ S)
{
    size_t i = (size_t)blockIdx.x * 256 + threadIdx.x;  // 8 weights / thread
    size_t base = i * 8;
    int n = (int)(base / K_TOTAL);
    int k = (int)(base % K_TOTAL);
    float sc = S[(size_t)n * (K_TOTAL / GROUPSZ) + (k >> 7)];

    float f[8];
    if (g_w_is_i32) {
        const int4* W = reinterpret_cast<const int4*>(Wv);
        int4 v0 = W[i * 2], v1 = W[i * 2 + 1];
        f[0] = (float)v0.x; f[1] = (float)v0.y; f[2] = (float)v0.z; f[3] = (float)v0.w;
        f[4] = (float)v1.x; f[5] = (float)v1.y; f[6] = (float)v1.z; f[7] = (float)v1.w;
    } else {
        uint2 raw = reinterpret_cast<const uint2*>(Wv)[i];
        const int8_t* b = reinterpret_cast<const int8_t*>(&raw);
#pragma unroll
        for (int j = 0; j < 8; j++) f[j] = (float)b[j];
    }
    __half2 h0 = __floats2half2_rn(f[0] * sc, f[1] * sc);
    __half2 h1 = __floats2half2_rn(f[2] * sc, f[3] * sc);
    __half2 h2 = __floats2half2_rn(f[4] * sc, f[5] * sc);
    __half2 h3 = __floats2half2_rn(f[6] * sc, f[7] * sc);
    uint4 pk;
    pk.x = *(const uint32_t*)&h0; pk.y = *(const uint32_t*)&h1;
    pk.z = *(const uint32_t*)&h2; pk.w = *(const uint32_t*)&h3;
    reinterpret_cast<uint4*>(g_Bh)[i] = pk;
}

// ---------------- HMMA GEMM: 128x256, 512 threads, 16 warps ----------------
__global__ __launch_bounds__(THREADS, 1) void wq8_gemm_kernel(
    const float* __restrict__ BIAS,
    float* __restrict__ O)
{
    extern __shared__ __align__(16) __half smem[];
    __half (*As)[BM][LDS_A] = reinterpret_cast<__half (*)[BM][LDS_A]>(smem);
    __half (*Bs)[BN][LDS_B] =
        reinterpret_cast<__half (*)[BN][LDS_B]>(smem + NSTAGE * BM * LDS_A);

    const int tid  = threadIdx.x;
    const int lane = tid & 31;
    const int warp = tid >> 5;
    const int wm   = warp >> 3;   // 0..1 : 64-row slab
    const int wn   = warp & 7;    // 0..7 : 32-col slab

    const int m0 = blockIdx.y * BM;
    const int n0 = blockIdx.x * BN;

    float acc[4][4][4];
#pragma unroll
    for (int i = 0; i < 4; i++)
#pragma unroll
        for (int j = 0; j < 4; j++)
#pragma unroll
            for (int k = 0; k < 4; k++) acc[i][j][k] = 0.f;

    // load plan (512 thr): A 128x64 halves = 1024 chunks -> 2/thr;
    // B 256x64 halves = 2048 chunks -> 4/thr
    const int l_row = tid >> 3;          // 0..63
    const int l_col = (tid & 7) * 8;     // half offset

    auto issue_stage = [&](int s, int kb) {
#pragma unroll
        for (int i = 0; i < 2; i++) {
            int row = l_row + i * 64;
            uint32_t d = smem_u32(&As[s][row][l_col]);
            CP_ASYNC_16(d, g_Ah + (size_t)(m0 + row) * K_TOTAL + kb + l_col);
        }
#pragma unroll
        for (int i = 0; i < 4; i++) {
            int row = l_row + i * 64;
            uint32_t d = smem_u32(&Bs[s][row][l_col]);
            CP_ASYNC_16(d, g_Bh + (size_t)(n0 + row) * K_TOTAL + kb + l_col);
        }
    };

    auto compute = [&](int s) {
#pragma unroll
        for (int ks = 0; ks < 4; ks++) {
            uint32_t af[4][4];
#pragma unroll
            for (int mi = 0; mi < 4; mi++) {
                const __half* p =
                    &As[s][wm * 64 + mi * 16 + (lane & 15)][ks * 16 + (lane >> 4) * 8];
                uint32_t addr = smem_u32(p);
                asm volatile(
                    "ldmatrix.sync.aligned.m8n8.x4.shared.b16 {%0,%1,%2,%3}, [%4];"
                    : "=r"(af[mi][0]), "=r"(af[mi][1]), "=r"(af[mi][2]), "=r"(af[mi][3])
                    : "r"(addr));
            }
            uint32_t bf[8];
#pragma unroll
            for (int bi = 0; bi < 2; bi++) {
                int mm = lane >> 3;
                int nr = wn * 32 + bi * 16 + ((mm >> 1) << 3) + (lane & 7);
                int kk = ks * 16 + ((mm & 1) << 3);
                uint32_t addr = smem_u32(&Bs[s][nr][kk]);
                asm volatile(
                    "ldmatrix.sync.aligned.m8n8.x4.shared.b16 {%0,%1,%2,%3}, [%4];"
                    : "=r"(bf[bi * 4]), "=r"(bf[bi * 4 + 1]),
                      "=r"(bf[bi * 4 + 2]), "=r"(bf[bi * 4 + 3])
                    : "r"(addr));
            }
#pragma unroll
            for (int mi = 0; mi < 4; mi++)
#pragma unroll
                for (int ni = 0; ni < 4; ni++) {
                    asm volatile(
                        "mma.sync.aligned.m16n8k16.row.col.f32.f16.f16.f32 "
                        "{%0,%1,%2,%3}, {%4,%5,%6,%7}, {%8,%9}, {%0,%1,%2,%3};"
                        : "+f"(acc[mi][ni][0]), "+f"(acc[mi][ni][1]),
                          "+f"(acc[mi][ni][2]), "+f"(acc[mi][ni][3])
                        : "r"(af[mi][0]), "r"(af[mi][1]), "r"(af[mi][2]), "r"(af[mi][3]),
                          "r"(bf[ni * 2]), "r"(bf[ni * 2 + 1]));
                }
        }
    };

    // prologue: fill 2 of 3 stages
#pragma unroll
    for (int s = 0; s < NSTAGE - 1; s++) {
        issue_stage(s, s * BK);
        CP_COMMIT();
    }

    // mainloop: single sync; cp.async for stage t+2 issued AFTER compute(t)
    // (measured better than issue-before: avoids MIO contention with the
    //  ldmatrix burst). Safe: sync(t) orders all threads past compute(t-1),
    //  the last reader of stage (t+2)%3.
    for (int t = 0; t < NT; t++) {
        CP_WAIT(NSTAGE - 2);     // stage t resident (1 group may stay pending)
        __syncthreads();
        compute(t % NSTAGE);
        if (t + NSTAGE - 1 < NT)
            issue_stage((t + NSTAGE - 1) % NSTAGE, (t + NSTAGE - 1) * BK);
        CP_COMMIT();             // empty group in tail keeps wait-count invariant
    }

    // ---- epilogue: f16(acc) + f16(bias), store f32 (matches reference rounding) ----
#pragma unroll
    for (int mi = 0; mi < 4; mi++) {
#pragma unroll
        for (int ni = 0; ni < 4; ni++) {
            int col = n0 + wn * 32 + ni * 8 + (lane & 3) * 2;
            float2 bf2 = *reinterpret_cast<const float2*>(BIAS + col);
            __half2 b2 = __floats2half2_rn(bf2.x, bf2.y);
            int r0 = m0 + wm * 64 + mi * 16 + (lane >> 2);

            __half2 v0 = __floats2half2_rn(acc[mi][ni][0], acc[mi][ni][1]);
            __half2 v1 = __floats2half2_rn(acc[mi][ni][2], acc[mi][ni][3]);
            float2 o0 = __half22float2(__hadd2(v0, b2));
            float2 o1 = __half22float2(__hadd2(v1, b2));
            *reinterpret_cast<float2*>(O + (size_t)r0 * N_TOTAL + col) = o0;
            *reinterpret_cast<float2*>(O + (size_t)(r0 + 8) * N_TOTAL + col) = o1;
        }
    }
}

extern "C" void kernel_launch(void* const* d_in, const int* in_sizes, int n_in,
                              void* d_out, int out_size)
{
    const float* x    = (const float*)d_in[0];
    const void*  w    = (const void*)d_in[1];
    const float* s    = (const float*)d_in[2];
    const float* bias = (const float*)d_in[3];
    float*       out  = (float*)d_out;

    cudaFuncSetAttribute(wq8_gemm_kernel,
                         cudaFuncAttributeMaxDynamicSharedMemorySize, SMEM_BYTES);

    probe_weight_kernel<<<1, 32>>>((const int8_t*)w);
    convert_x_kernel<<<(int)((size_t)M_TOTAL * K_TOTAL / 8 / 256), 256>>>(
        (const float4*)x);
    dequant_w_kernel<<<(int)((size_t)N_TOTAL * K_TOTAL / 8 / 256), 256>>>(w, s);

    dim3 grid(N_TOTAL / BN, M_TOTAL / BM);  // 43 x 64
    wq8_gemm_kernel<<<grid, THREADS, SMEM_BYTES>>>(bias, out);
}

// round 13
// speedup vs baseline: 1.1986x; 1.1223x over previous
#include <cuda_runtime.h>
#include <cuda_fp16.h>
#include <cstdint>

// out[m,n] = f32( f16( f32x[m,:] . (W[n,:]*scale) ) + f16(bias[n]) )
// Harness dtypes: x f32 [M,K], weight i32-or-i8 (probed) [N,K],
// scale f32 [N,K/128], bias f32 [N], out f32 [M,N]
// compute_103 virtual arch: NO tcgen05. Ceiling = legacy HMMA.
// R8: R7 shape (128x256x64, 512thr, 16 warps) + unrolled 4-stage pipeline with
//     compile-time stage offsets and fully hoisted address arithmetic.

#define M_TOTAL 8192
#define N_TOTAL 11008
#define K_TOTAL 4096
#define GROUPSZ 128

#define BM 128
#define BN 256
#define BK 64
#define NSTAGE 4
#define NT (K_TOTAL / BK)   // 64
#define LDS_A 72            // 64 + 8 pad halves; conflict-free ldmatrix
#define LDS_B 72
#define THREADS 512

#define STRIDE_A ((uint32_t)(BM * LDS_A * 2))            // 18432 B / stage
#define STRIDE_B ((uint32_t)(BN * LDS_B * 2))            // 36864 B / stage
#define B_BASE   (NSTAGE * STRIDE_A)                     // 73728
#define SMEM_BYTES (B_BASE + NSTAGE * STRIDE_B)          // 221184 (fits 227KB)

// ---------------- scratch (f16 prepass outputs) ----------------
__device__ __half g_Ah[(size_t)M_TOTAL * K_TOTAL];   // 64 MB
__device__ __half g_Bh[(size_t)N_TOTAL * K_TOTAL];   // 88 MB
__device__ int    g_w_is_i32;

__device__ __forceinline__ uint32_t smem_u32(const void* p) {
    uint32_t a;
    asm("{ .reg .u64 t; cvta.to.shared.u64 t, %1; cvt.u32.u64 %0, t; }"
        : "=r"(a) : "l"(p));
    return a;
}

#define CP_ASYNC_16(dst_u32, src_ptr) \
    asm volatile("cp.async.cg.shared.global [%0], [%1], 16;" \
                 :: "r"(dst_u32), "l"(src_ptr) : "memory")
#define CP_COMMIT() asm volatile("cp.async.commit_group;" ::: "memory")
#define CP_WAIT(n)  asm volatile("cp.async.wait_group %0;" :: "n"(n) : "memory")

// ---------------- dtype probe ----------------
__global__ void probe_weight_kernel(const int8_t* __restrict__ w)
{
    if (threadIdx.x != 0 || blockIdx.x != 0) return;
    int votes = 0;
#pragma unroll
    for (int i = 0; i < 16; i++) {
        int8_t b0 = w[i * 4 + 0], b1 = w[i * 4 + 1], b2 = w[i * 4 + 2], b3 = w[i * 4 + 3];
        int8_t ext = (b0 < 0) ? (int8_t)-1 : (int8_t)0;
        if (b1 == ext && b2 == ext && b3 == ext) votes++;
    }
    g_w_is_i32 = (votes >= 14) ? 1 : 0;
}

// ---------------- prepass: x f32 -> f16 ----------------
__global__ __launch_bounds__(256) void convert_x_kernel(const float4* __restrict__ X)
{
    size_t i = (size_t)blockIdx.x * 256 + threadIdx.x;
    float4 a = X[2 * i], b = X[2 * i + 1];
    __half2 h0 = __floats2half2_rn(a.x, a.y);
    __half2 h1 = __floats2half2_rn(a.z, a.w);
    __half2 h2 = __floats2half2_rn(b.x, b.y);
    __half2 h3 = __floats2half2_rn(b.z, b.w);
    uint4 pk;
    pk.x = *(const uint32_t*)&h0; pk.y = *(const uint32_t*)&h1;
    pk.z = *(const uint32_t*)&h2; pk.w = *(const uint32_t*)&h3;
    reinterpret_cast<uint4*>(g_Ah)[i] = pk;
}

// ---------------- prepass: W dequant -> f16 ----------------
__global__ __launch_bounds__(256) void dequant_w_kernel(const void* __restrict__ Wv,
                                                        const float* __restrict__ S)
{
    size_t i = (size_t)blockIdx.x * 256 + threadIdx.x;
    size_t base = i * 8;
    int n = (int)(base / K_TOTAL);
    int k = (int)(base % K_TOTAL);
    float sc = S[(size_t)n * (K_TOTAL / GROUPSZ) + (k >> 7)];

    float f[8];
    if (g_w_is_i32) {
        const int4* W = reinterpret_cast<const int4*>(Wv);
        int4 v0 = W[i * 2], v1 = W[i * 2 + 1];
        f[0] = (float)v0.x; f[1] = (float)v0.y; f[2] = (float)v0.z; f[3] = (float)v0.w;
        f[4] = (float)v1.x; f[5] = (float)v1.y; f[6] = (float)v1.z; f[7] = (float)v1.w;
    } else {
        uint2 raw = reinterpret_cast<const uint2*>(Wv)[i];
        const int8_t* b = reinterpret_cast<const int8_t*>(&raw);
#pragma unroll
        for (int j = 0; j < 8; j++) f[j] = (float)b[j];
    }
    __half2 h0 = __floats2half2_rn(f[0] * sc, f[1] * sc);
    __half2 h1 = __floats2half2_rn(f[2] * sc, f[3] * sc);
    __half2 h2 = __floats2half2_rn(f[4] * sc, f[5] * sc);
    __half2 h3 = __floats2half2_rn(f[6] * sc, f[7] * sc);
    uint4 pk;
    pk.x = *(const uint32_t*)&h0; pk.y = *(const uint32_t*)&h1;
    pk.z = *(const uint32_t*)&h2; pk.w = *(const uint32_t*)&h3;
    reinterpret_cast<uint4*>(g_Bh)[i] = pk;
}

// ---------------- HMMA GEMM: 128x256, 512 thr, 4-stage unrolled pipeline -------
__global__ __launch_bounds__(THREADS, 1) void wq8_gemm_kernel(
    const float* __restrict__ BIAS,
    float* __restrict__ O)
{
    extern __shared__ __align__(16) __half smem[];
    const uint32_t sb = smem_u32(smem);

    const int tid  = threadIdx.x;
    const int lane = tid & 31;
    const int warp = tid >> 5;
    const int wm   = warp >> 3;   // 0..1 : 64-row slab
    const int wn   = warp & 7;    // 0..7 : 32-col slab

    const int m0 = blockIdx.y * BM;
    const int n0 = blockIdx.x * BN;

    float acc[4][4][4];
#pragma unroll
    for (int i = 0; i < 4; i++)
#pragma unroll
        for (int j = 0; j < 4; j++)
#pragma unroll
            for (int k = 0; k < 4; k++) acc[i][j][k] = 0.f;

    // ---- hoisted per-thread addressing ----
    // loader plan: A 128x64 halves -> 2 chunks/thr; B 256x64 -> 4 chunks/thr
    const int l_row = tid >> 3;          // 0..63
    const int l_col = (tid & 7) * 8;     // half offset

    uint32_t sa_off[2], sbo_off[4];      // smem STS targets (stage 0)
    const __half* ga[2];                 // gmem read cursors (advance BK/issue)
    const __half* gb[4];
#pragma unroll
    for (int i = 0; i < 2; i++) {
        int row = l_row + i * 64;
        sa_off[i] = sb + (uint32_t)(row * LDS_A + l_col) * 2;
        ga[i] = g_Ah + (size_t)(m0 + row) * K_TOTAL + l_col;
    }
#pragma unroll
    for (int i = 0; i < 4; i++) {
        int row = l_row + i * 64;
        sbo_off[i] = sb + B_BASE + (uint32_t)(row * LDS_B + l_col) * 2;
        gb[i] = g_Bh + (size_t)(n0 + row) * K_TOTAL + l_col;
    }

    // fragment LDSM base addresses (stage 0, ks 0)
    uint32_t a_off[4], b_off[2];
#pragma unroll
    for (int mi = 0; mi < 4; mi++)
        a_off[mi] = sb + (uint32_t)((wm * 64 + mi * 16 + (lane & 15)) * LDS_A +
                                    (lane >> 4) * 8) * 2;
    {
        int mm = lane >> 3;
#pragma unroll
        for (int bi = 0; bi < 2; bi++) {
            int nr = wn * 32 + bi * 16 + ((mm >> 1) << 3) + (lane & 7);
            b_off[bi] = sb + B_BASE +
                        (uint32_t)(nr * LDS_B + ((mm & 1) << 3)) * 2;
        }
    }

    auto issue_stage = [&](uint32_t offA, uint32_t offB) {
#pragma unroll
        for (int i = 0; i < 2; i++) {
            CP_ASYNC_16(sa_off[i] + offA, ga[i]);
            ga[i] += BK;
        }
#pragma unroll
        for (int i = 0; i < 4; i++) {
            CP_ASYNC_16(sbo_off[i] + offB, gb[i]);
            gb[i] += BK;
        }
    };

    auto compute = [&](uint32_t offA, uint32_t offB) {
#pragma unroll
        for (int ks = 0; ks < 4; ks++) {
            uint32_t af[4][4];
#pragma unroll
            for (int mi = 0; mi < 4; mi++) {
                uint32_t addr = a_off[mi] + offA + ks * 32;
                asm volatile(
                    "ldmatrix.sync.aligned.m8n8.x4.shared.b16 {%0,%1,%2,%3}, [%4];"
                    : "=r"(af[mi][0]), "=r"(af[mi][1]), "=r"(af[mi][2]), "=r"(af[mi][3])
                    : "r"(addr));
            }
            uint32_t bf[8];
#pragma unroll
            for (int bi = 0; bi < 2; bi++) {
                uint32_t addr = b_off[bi] + offB + ks * 32;
                asm volatile(
                    "ldmatrix.sync.aligned.m8n8.x4.shared.b16 {%0,%1,%2,%3}, [%4];"
                    : "=r"(bf[bi * 4]), "=r"(bf[bi * 4 + 1]),
                      "=r"(bf[bi * 4 + 2]), "=r"(bf[bi * 4 + 3])
                    : "r"(addr));
            }
#pragma unroll
            for (int mi = 0; mi < 4; mi++)
#pragma unroll
                for (int ni = 0; ni < 4; ni++) {
                    asm volatile(
                        "mma.sync.aligned.m16n8k16.row.col.f32.f16.f16.f32 "
                        "{%0,%1,%2,%3}, {%4,%5,%6,%7}, {%8,%9}, {%0,%1,%2,%3};"
                        : "+f"(acc[mi][ni][0]), "+f"(acc[mi][ni][1]),
                          "+f"(acc[mi][ni][2]), "+f"(acc[mi][ni][3])
                        : "r"(af[mi][0]), "r"(af[mi][1]), "r"(af[mi][2]), "r"(af[mi][3]),
                          "r"(bf[ni * 2]), "r"(bf[ni * 2 + 1]));
                }
        }
    };

    // prologue: fill 3 of 4 stages
    issue_stage(0 * STRIDE_A, 0 * STRIDE_B); CP_COMMIT();
    issue_stage(1 * STRIDE_A, 1 * STRIDE_B); CP_COMMIT();
    issue_stage(2 * STRIDE_A, 2 * STRIDE_B); CP_COMMIT();

    int next = 3;  // next k-block to issue; stage pattern per body is static

    // body: wait(<=2 pending) -> stage t resident; sync; compute(t);
    // issue k-block t+3 into stage (t+3)&3; commit (empty in tail).
#define BODY(CUR, NXT)                                                        \
    do {                                                                      \
        CP_WAIT(2);                                                           \
        __syncthreads();                                                      \
        compute((CUR) * STRIDE_A, (CUR) * STRIDE_B);                          \
        if (next < NT) {                                                      \
            issue_stage((NXT) * STRIDE_A, (NXT) * STRIDE_B);                  \
            next++;                                                           \
        }                                                                     \
        CP_COMMIT();                                                          \
    } while (0)

#pragma unroll 1
    for (int tu = 0; tu < NT / 4; tu++) {
        BODY(0, 3);
        BODY(1, 0);
        BODY(2, 1);
        BODY(3, 2);
    }
#undef BODY

    // ---- epilogue: f16(acc) + f16(bias), store f32 (matches reference rounding) ----
#pragma unroll
    for (int mi = 0; mi < 4; mi++) {
#pragma unroll
        for (int ni = 0; ni < 4; ni++) {
            int col = n0 + wn * 32 + ni * 8 + (lane & 3) * 2;
            float2 bf2 = *reinterpret_cast<const float2*>(BIAS + col);
            __half2 b2 = __floats2half2_rn(bf2.x, bf2.y);
            int r0 = m0 + wm * 64 + mi * 16 + (lane >> 2);

            __half2 v0 = __floats2half2_rn(acc[mi][ni][0], acc[mi][ni][1]);
            __half2 v1 = __floats2half2_rn(acc[mi][ni][2], acc[mi][ni][3]);
            float2 o0 = __half22float2(__hadd2(v0, b2));
            float2 o1 = __half22float2(__hadd2(v1, b2));
            *reinterpret_cast<float2*>(O + (size_t)r0 * N_TOTAL + col) = o0;
            *reinterpret_cast<float2*>(O + (size_t)(r0 + 8) * N_TOTAL + col) = o1;
        }
    }
}

extern "C" void kernel_launch(void* const* d_in, const int* in_sizes, int n_in,
                              void* d_out, int out_size)
{
    const float* x    = (const float*)d_in[0];
    const void*  w    = (const void*)d_in[1];
    const float* s    = (const float*)d_in[2];
    const float* bias = (const float*)d_in[3];
    float*       out  = (float*)d_out;

    cudaFuncSetAttribute(wq8_gemm_kernel,
                         cudaFuncAttributeMaxDynamicSharedMemorySize, SMEM_BYTES);

    probe_weight_kernel<<<1, 32>>>((const int8_t*)w);
    convert_x_kernel<<<(int)((size_t)M_TOTAL * K_TOTAL / 8 / 256), 256>>>(
        (const float4*)x);
    dequant_w_kernel<<<(int)((size_t)N_TOTAL * K_TOTAL / 8 / 256), 256>>>(w, s);

    dim3 grid(N_TOTAL / BN, M_TOTAL / BM);  // 43 x 64
    wq8_gemm_kernel<<<grid, THREADS, SMEM_BYTES>>>(bias, out);
}